// round 8
// baseline (speedup 1.0000x reference)
#include <cuda_runtime.h>
#include <cuda_bf16.h>
#include <cstdint>

#define BATCH 4
#define DKDIM 128
#define DVDIM 512
#define NQ 4096
#define NM 8192
#define NCHUNK (NM / 64)
#define KL2E (0.08838834764831843f * 1.4426950408889634f)

// Pre-converted bf16 operands (device globals, allocation-guard-safe)
__device__ __nv_bfloat16 g_KT[(size_t)BATCH * NM * DKDIM];   // [b][m][d]
__device__ __nv_bfloat16 g_VT[(size_t)BATCH * DVDIM * NM];   // [b][dv][m]
__device__ int g_valid[BATCH];

static __device__ __forceinline__ void mma16816(float c[4], uint32_t a0, uint32_t a1,
                                                uint32_t a2, uint32_t a3,
                                                uint32_t b0, uint32_t b1) {
    asm volatile(
        "mma.sync.aligned.m16n8k16.row.col.f32.bf16.bf16.f32 "
        "{%0,%1,%2,%3}, {%4,%5,%6,%7}, {%8,%9}, {%0,%1,%2,%3};\n"
        : "+f"(c[0]), "+f"(c[1]), "+f"(c[2]), "+f"(c[3])
        : "r"(a0), "r"(a1), "r"(a2), "r"(a3), "r"(b0), "r"(b1));
}

#define LDSM4(r0, r1, r2, r3, addr)                                          \
    asm volatile(                                                            \
        "ldmatrix.sync.aligned.m8n8.x4.shared.b16 {%0,%1,%2,%3}, [%4];"      \
        : "=r"(r0), "=r"(r1), "=r"(r2), "=r"(r3) : "r"(addr))

static __device__ __forceinline__ float ex2f(float x) {
    float y;
    asm("ex2.approx.ftz.f32 %0, %1;" : "=f"(y) : "f"(x));
    return y;
}

static __device__ __forceinline__ uint32_t bpack(float lo, float hi) {
    __nv_bfloat162 h = __floats2bfloat162_rn(lo, hi);
    return *reinterpret_cast<uint32_t*>(&h);
}

#define CPA16(dst, src) \
    asm volatile("cp.async.ca.shared.global [%0], [%1], 16;\n" :: "r"(dst), "l"(src))
#define CPA_COMMIT() asm volatile("cp.async.commit_group;\n")
#define CPA_WAIT2() asm volatile("cp.async.wait_group 2;\n")

// ---------------- K0a: transpose+convert mkey -> g_KT[b][m][d] ----------------
__global__ void __launch_bounds__(256) convk_kernel(const float* __restrict__ mk) {
    __shared__ float tile[32][33];
    const int b = blockIdx.z;
    const int m0 = blockIdx.x * 32, d0 = blockIdx.y * 32;
    const int tx = threadIdx.x & 31, ty = threadIdx.x >> 5;
    const float* src = mk + ((size_t)b * DKDIM + d0) * NM + m0;
#pragma unroll
    for (int i = ty; i < 32; i += 8) tile[i][tx] = src[(size_t)i * NM + tx];
    __syncthreads();
    __nv_bfloat16* dst = g_KT + ((size_t)b * NM + m0) * DKDIM + d0;
#pragma unroll
    for (int i = ty; i < 32; i += 8)
        dst[(size_t)i * DKDIM + tx] = __float2bfloat16(tile[tx][i]);
}

// ---------------- K0b: convert mval -> g_VT (same layout) ----------------
__global__ void __launch_bounds__(256) convv_kernel(const float* __restrict__ mv) {
    const size_t i = ((size_t)blockIdx.x * 256 + threadIdx.x) * 4;
    float4 v = *(const float4*)&mv[i];
    uint2 pk = make_uint2(bpack(v.x, v.y), bpack(v.z, v.w));
    *(uint2*)&g_VT[i] = pk;
}

// ---------------- K0c: per-batch validity flags ----------------
__global__ void valid_kernel(const uint32_t* __restrict__ qm,
                             const uint32_t* __restrict__ mm) {
    int b = blockIdx.x;
    int aq = 0, am = 0;
    for (int i = threadIdx.x; i < NQ; i += blockDim.x) aq |= (qm[b * NQ + i] != 0);
    for (int i = threadIdx.x; i < NM; i += blockDim.x) am |= (mm[b * NM + i] != 0);
    aq = __syncthreads_or(aq);
    am = __syncthreads_or(am);
    if (threadIdx.x == 0) g_valid[b] = (aq && am) ? 1 : 0;
}

// ---------------- smem layout: 4-stage K/V, double-buffered P ----------------
#define KSZB (64 * 136 * 2)             // 17408/stage, pitch 272B
#define VSZB (128 * 72 * 2)             // 18432/stage, pitch 144B
#define PSZB (128 * 144)                // 18432/buffer, pitch 144B (16B-aligned rows)
#define KOFF 0
#define VOFF (4 * KSZB)                 // 69632
#define POFF (VOFF + 4 * VSZB)          // 143360
#define MOFF (POFF + 2 * PSZB)          // 180224
#define LOFF (MOFF + 4 * 256)           // 181248
#define SMEM_TOTAL (LOFF + 1024)        // 182272

// ---------------- Fused flash kernel: 2-D warp tile, P via smem ----------------
__global__ void __launch_bounds__(256) flash_kernel(
    const float* __restrict__ qkey, const float* __restrict__ qval,
    const uint32_t* __restrict__ qmask, const uint32_t* __restrict__ mmask,
    float* __restrict__ out) {
    extern __shared__ char smem[];
    float* maskf = (float*)(smem + MOFF);
    float* lsh = (float*)(smem + LOFF);
    const uint32_t smem_u32 = (uint32_t)__cvta_generic_to_shared(smem);

    const int tid = threadIdx.x;
    const int lane = tid & 31, warp = tid >> 5;
    const int g = lane >> 2, t = lane & 3;
    const int qg = warp & 3;    // q-group: rows 32*qg .. +32
    const int half = warp >> 2; // QK m-half / PV dv-half
    const int b = blockIdx.z;
    const int qbase = blockIdx.x * 128;
    const int dvbase = blockIdx.y * 128;

    // B-operand ldmatrix lane offsets (16 rows, alternating +16B col)
    const int lrow = (lane >> 4) * 8 + (lane & 7);
    const int lcol = ((lane >> 3) & 1) * 16;
    const uint32_t koff_l = (uint32_t)(lrow * 272 + lcol);
    const uint32_t voff_l = (uint32_t)(lrow * 144 + lcol);
    // A-operand ldmatrix lane offsets (rows 0-15, then +16B col)
    const uint32_t paoff_l = (uint32_t)((lane & 15) * 144 + (lane >> 4) * 16);

    // Persistent Q fragments: 32q x 128d -> [8 ksteps][2 mtiles][4] = 64 regs
    uint32_t aq[8][2][4];
    {
        const float* qkb = qkey + (size_t)b * DKDIM * NQ;
#pragma unroll
        for (int mt = 0; mt < 2; mt++) {
            const int q0g = qbase + 32 * qg + 16 * mt + g;
#pragma unroll
            for (int ks = 0; ks < 8; ks++) {
                const int d0 = ks * 16 + 2 * t;
                const float* p0 = qkb + (size_t)d0 * NQ + q0g;
                const float* p8 = p0 + (size_t)8 * NQ;
                aq[ks][mt][0] = bpack(p0[0], p0[NQ]);
                aq[ks][mt][1] = bpack(p0[8], p0[NQ + 8]);
                aq[ks][mt][2] = bpack(p8[0], p8[NQ]);
                aq[ks][mt][3] = bpack(p8[8], p8[NQ + 8]);
            }
        }
    }

    const __nv_bfloat16* ksrc_b = g_KT + (size_t)b * NM * DKDIM;
    const __nv_bfloat16* vsrc_b = g_VT + ((size_t)b * DVDIM + dvbase) * NM;
    const uint32_t* mmb = mmask + b * NM;

#define PREFETCH(ct)                                                           \
    do {                                                                       \
        const int bufi = (ct) & 3;                                             \
        const char* ksrc = (const char*)(ksrc_b + (size_t)(ct) * 64 * DKDIM);  \
        const uint32_t kdst = smem_u32 + KOFF + bufi * KSZB;                   \
        _Pragma("unroll") for (int k = 0; k < 4; k++) {                        \
            int idx = tid + k * 256;                                           \
            int m = idx >> 4, j = idx & 15;                                    \
            CPA16(kdst + m * 272 + j * 16, ksrc + m * 256 + j * 16);           \
        }                                                                      \
        const char* vsrc = (const char*)(vsrc_b + (size_t)(ct) * 64);          \
        const uint32_t vdst = smem_u32 + VOFF + bufi * VSZB;                   \
        _Pragma("unroll") for (int k = 0; k < 4; k++) {                        \
            int idx = tid + k * 256;                                           \
            int dv = idx >> 3, j = idx & 7;                                    \
            CPA16(vdst + dv * 144 + j * 16,                                    \
                  vsrc + (size_t)dv * (NM * 2) + j * 16);                      \
        }                                                                      \
        if (tid < 64)                                                          \
            maskf[bufi * 64 + tid] = (mmb[(ct) * 64 + tid] != 0) ? 1.f : 0.f;  \
    } while (0)

    float lac[4] = {0.f, 0.f, 0.f, 0.f};  // rows g, g+8, 16+g, 24+g of q-group
    float oacc[2][8][4];
#pragma unroll
    for (int mt = 0; mt < 2; mt++)
#pragma unroll
        for (int j = 0; j < 8; j++)
#pragma unroll
            for (int c = 0; c < 4; c++) oacc[mt][j][c] = 0.f;

    // ---- QK + softmax numerator for chunk ct -> P[(ct)&1] ----
#define QK_PHASE(ct)                                                              \
    do {                                                                          \
        const int bufi = (ct) & 3;                                                \
        const uint32_t kfb =                                                      \
            smem_u32 + KOFF + bufi * KSZB + half * (32 * 272) + koff_l;           \
        float sc[2][4][4];                                                        \
        _Pragma("unroll") for (int mt = 0; mt < 2; mt++)                          \
            _Pragma("unroll") for (int j = 0; j < 4; j++)                         \
                _Pragma("unroll") for (int c = 0; c < 4; c++) sc[mt][j][c] = 0.f; \
        _Pragma("unroll") for (int ks = 0; ks < 8; ks++) {                        \
            _Pragma("unroll") for (int jp = 0; jp < 2; jp++) {                    \
                uint32_t b0a, b1a, b0b, b1b;                                      \
                LDSM4(b0a, b1a, b0b, b1b, kfb + jp * (16 * 272) + ks * 32);       \
                mma16816(sc[0][2 * jp], aq[ks][0][0], aq[ks][0][1],               \
                         aq[ks][0][2], aq[ks][0][3], b0a, b1a);                   \
                mma16816(sc[0][2 * jp + 1], aq[ks][0][0], aq[ks][0][1],           \
                         aq[ks][0][2], aq[ks][0][3], b0b, b1b);                   \
                mma16816(sc[1][2 * jp], aq[ks][1][0], aq[ks][1][1],               \
                         aq[ks][1][2], aq[ks][1][3], b0a, b1a);                   \
                mma16816(sc[1][2 * jp + 1], aq[ks][1][0], aq[ks][1][1],           \
                         aq[ks][1][2], aq[ks][1][3], b0b, b1b);                   \
            }                                                                     \
        }                                                                         \
        const float* mf = maskf + bufi * 64 + half * 32;                          \
        char* Pw = smem + POFF + ((ct) & 1) * PSZB;                               \
        _Pragma("unroll") for (int mt = 0; mt < 2; mt++) {                        \
            _Pragma("unroll") for (int j = 0; j < 4; j++) {                       \
                const float mf0 = mf[8 * j + 2 * t];                              \
                const float mf1 = mf[8 * j + 2 * t + 1];                          \
                float p0 = ex2f(sc[mt][j][0] * KL2E) * mf0;                       \
                float p1 = ex2f(sc[mt][j][1] * KL2E) * mf1;                       \
                float p2 = ex2f(sc[mt][j][2] * KL2E) * mf0;                       \
                float p3 = ex2f(sc[mt][j][3] * KL2E) * mf1;                       \
                lac[2 * mt] += p0 + p1;                                           \
                lac[2 * mt + 1] += p2 + p3;                                       \
                const int col2 = (32 * half + 8 * j + 2 * t) * 2;                 \
                const int r0 = 32 * qg + 16 * mt + g;                             \
                *(uint32_t*)(Pw + r0 * 144 + col2) = bpack(p0, p1);               \
                *(uint32_t*)(Pw + (r0 + 8) * 144 + col2) = bpack(p2, p3);         \
            }                                                                     \
        }                                                                         \
    } while (0)

    // ---- PV for chunk ct: O += P[(ct)&1] x V[(ct)&3] ----
#define PV_PHASE(ct)                                                              \
    do {                                                                          \
        const int bufi = (ct) & 3;                                                \
        const uint32_t vfb =                                                      \
            smem_u32 + VOFF + bufi * VSZB + half * (64 * 144) + voff_l;           \
        const uint32_t pb0 = smem_u32 + POFF + ((ct) & 1) * PSZB +                \
                             (32 * qg) * 144 + paoff_l;                           \
        _Pragma("unroll") for (int km = 0; km < 4; km++) {                        \
            uint32_t ap0[4], ap1[4];                                              \
            LDSM4(ap0[0], ap0[1], ap0[2], ap0[3], pb0 + km * 32);                 \
            LDSM4(ap1[0], ap1[1], ap1[2], ap1[3], pb0 + 16 * 144 + km * 32);      \
            _Pragma("unroll") for (int jp = 0; jp < 4; jp++) {                    \
                uint32_t b0a, b1a, b0b, b1b;                                      \
                LDSM4(b0a, b1a, b0b, b1b, vfb + jp * (16 * 144) + km * 32);       \
                mma16816(oacc[0][2 * jp], ap0[0], ap0[1], ap0[2], ap0[3],         \
                         b0a, b1a);                                               \
                mma16816(oacc[0][2 * jp + 1], ap0[0], ap0[1], ap0[2], ap0[3],     \
                         b0b, b1b);                                               \
                mma16816(oacc[1][2 * jp], ap1[0], ap1[1], ap1[2], ap1[3],         \
                         b0a, b1a);                                               \
                mma16816(oacc[1][2 * jp + 1], ap1[0], ap1[1], ap1[2], ap1[3],     \
                         b0b, b1b);                                               \
            }                                                                     \
        }                                                                         \
    } while (0)

    PREFETCH(0);
    CPA_COMMIT();
    PREFETCH(1);
    CPA_COMMIT();

    for (int ct = 0; ct < NCHUNK; ct++) {
        if (ct + 2 < NCHUNK) PREFETCH(ct + 2);
        CPA_COMMIT();
        CPA_WAIT2();
        __syncthreads();

        if (half == 0) {
            QK_PHASE(ct);
            if (ct > 0) PV_PHASE(ct - 1);
        } else {
            if (ct > 0) PV_PHASE(ct - 1);
            QK_PHASE(ct);
        }
    }

    __syncthreads();  // P[last] from both producers visible
    PV_PHASE(NCHUNK - 1);

    // ---- epilogue: combine l halves, normalize, add qv ----
#pragma unroll
    for (int i = 0; i < 4; i++) {
        lac[i] += __shfl_xor_sync(0xffffffffu, lac[i], 1);
        lac[i] += __shfl_xor_sync(0xffffffffu, lac[i], 2);
    }
    if (t == 0) {
        lsh[warp * 32 + g] = lac[0];
        lsh[warp * 32 + 8 + g] = lac[1];
        lsh[warp * 32 + 16 + g] = lac[2];
        lsh[warp * 32 + 24 + g] = lac[3];
    }
    __syncthreads();

    const int vb = g_valid[b];
    const float* qvb = qval + (size_t)b * DVDIM * NQ;
    float* ob = out + (size_t)b * DVDIM * NQ;
#pragma unroll
    for (int mt = 0; mt < 2; mt++) {
        const int r0 = 16 * mt + g;           // local row in q-group
        const int qr0 = qbase + 32 * qg + r0;
        const int qr1 = qr0 + 8;
        const float lt0 = lsh[qg * 32 + r0] + lsh[(qg + 4) * 32 + r0];
        const float lt1 = lsh[qg * 32 + r0 + 8] + lsh[(qg + 4) * 32 + r0 + 8];
        const float f0 = (vb != 0 && qmask[b * NQ + qr0] != 0) ? 1.f / lt0 : 0.f;
        const float f1 = (vb != 0 && qmask[b * NQ + qr1] != 0) ? 1.f / lt1 : 0.f;
#pragma unroll
        for (int j = 0; j < 8; j++) {
            const int dv = dvbase + 64 * half + 8 * j + 2 * t;
            const size_t A0 = (size_t)dv * NQ;
            ob[A0 + qr0] = qvb[A0 + qr0] + oacc[mt][j][0] * f0;
            ob[A0 + NQ + qr0] = qvb[A0 + NQ + qr0] + oacc[mt][j][1] * f0;
            ob[A0 + qr1] = qvb[A0 + qr1] + oacc[mt][j][2] * f1;
            ob[A0 + NQ + qr1] = qvb[A0 + NQ + qr1] + oacc[mt][j][3] * f1;
        }
    }
}

extern "C" void kernel_launch(void* const* d_in, const int* in_sizes, int n_in,
                              void* d_out, int out_size) {
    const float* qkey = (const float*)d_in[0];
    const float* qval = (const float*)d_in[1];
    const uint32_t* qmask = (const uint32_t*)d_in[2];
    const float* mkey = (const float*)d_in[3];
    const float* mval = (const float*)d_in[4];
    const uint32_t* mmask = (const uint32_t*)d_in[5];
    float* out = (float*)d_out;

    static bool attr_set = false;
    if (!attr_set) {
        cudaFuncSetAttribute(flash_kernel,
                             cudaFuncAttributeMaxDynamicSharedMemorySize,
                             SMEM_TOTAL);
        attr_set = true;
    }

    convk_kernel<<<dim3(NM / 32, DKDIM / 32, BATCH), 256>>>(mkey);
    convv_kernel<<<(unsigned)((size_t)BATCH * DVDIM * NM / 4 / 256), 256>>>(mval);
    valid_kernel<<<BATCH, 256>>>(qmask, mmask);
    flash_kernel<<<dim3(NQ / 128, DVDIM / 128, BATCH), 256, SMEM_TOTAL>>>(
        qkey, qval, qmask, mmask, out);
}

// round 9
// speedup vs baseline: 1.0966x; 1.0966x over previous
#include <cuda_runtime.h>
#include <cuda_bf16.h>
#include <cstdint>

#define BATCH 4
#define DKDIM 128
#define DVDIM 512
#define NQ 4096
#define NM 8192
#define NCHUNK (NM / 64)
#define KL2E (0.08838834764831843f * 1.4426950408889634f)

// Pre-converted bf16 operands (device globals, allocation-guard-safe)
__device__ __nv_bfloat16 g_KT[(size_t)BATCH * NM * DKDIM];   // [b][m][d]
__device__ __nv_bfloat16 g_VT[(size_t)BATCH * DVDIM * NM];   // [b][dv][m]
__device__ int g_valid[BATCH];

static __device__ __forceinline__ void mma16816(float c[4], uint32_t a0, uint32_t a1,
                                                uint32_t a2, uint32_t a3,
                                                uint32_t b0, uint32_t b1) {
    asm volatile(
        "mma.sync.aligned.m16n8k16.row.col.f32.bf16.bf16.f32 "
        "{%0,%1,%2,%3}, {%4,%5,%6,%7}, {%8,%9}, {%0,%1,%2,%3};\n"
        : "+f"(c[0]), "+f"(c[1]), "+f"(c[2]), "+f"(c[3])
        : "r"(a0), "r"(a1), "r"(a2), "r"(a3), "r"(b0), "r"(b1));
}

#define LDSM4(r0, r1, r2, r3, addr)                                          \
    asm volatile(                                                            \
        "ldmatrix.sync.aligned.m8n8.x4.shared.b16 {%0,%1,%2,%3}, [%4];"      \
        : "=r"(r0), "=r"(r1), "=r"(r2), "=r"(r3) : "r"(addr))

static __device__ __forceinline__ float ex2f(float x) {
    float y;
    asm("ex2.approx.ftz.f32 %0, %1;" : "=f"(y) : "f"(x));
    return y;
}

static __device__ __forceinline__ uint32_t bpack(float lo, float hi) {
    __nv_bfloat162 h = __floats2bfloat162_rn(lo, hi);
    return *reinterpret_cast<uint32_t*>(&h);
}

#define CPA16(dst, src) \
    asm volatile("cp.async.ca.shared.global [%0], [%1], 16;\n" :: "r"(dst), "l"(src))
#define CPA_COMMIT() asm volatile("cp.async.commit_group;\n")
#define CPA_WAIT0() asm volatile("cp.async.wait_group 0;\n")

// ---------------- K0a: transpose+convert mkey -> g_KT[b][m][d] ----------------
__global__ void __launch_bounds__(256) convk_kernel(const float* __restrict__ mk) {
    __shared__ float tile[32][33];
    const int b = blockIdx.z;
    const int m0 = blockIdx.x * 32, d0 = blockIdx.y * 32;
    const int tx = threadIdx.x & 31, ty = threadIdx.x >> 5;
    const float* src = mk + ((size_t)b * DKDIM + d0) * NM + m0;
#pragma unroll
    for (int i = ty; i < 32; i += 8) tile[i][tx] = src[(size_t)i * NM + tx];
    __syncthreads();
    __nv_bfloat16* dst = g_KT + ((size_t)b * NM + m0) * DKDIM + d0;
#pragma unroll
    for (int i = ty; i < 32; i += 8)
        dst[(size_t)i * DKDIM + tx] = __float2bfloat16(tile[tx][i]);
}

// ---------------- K0b: convert mval -> g_VT (same layout) ----------------
__global__ void __launch_bounds__(256) convv_kernel(const float* __restrict__ mv) {
    const size_t i = ((size_t)blockIdx.x * 256 + threadIdx.x) * 4;
    float4 v = *(const float4*)&mv[i];
    uint2 pk = make_uint2(bpack(v.x, v.y), bpack(v.z, v.w));
    *(uint2*)&g_VT[i] = pk;
}

// ---------------- K0c: per-batch validity flags ----------------
__global__ void valid_kernel(const uint32_t* __restrict__ qm,
                             const uint32_t* __restrict__ mm) {
    int b = blockIdx.x;
    int aq = 0, am = 0;
    for (int i = threadIdx.x; i < NQ; i += blockDim.x) aq |= (qm[b * NQ + i] != 0);
    for (int i = threadIdx.x; i < NM; i += blockDim.x) am |= (mm[b * NM + i] != 0);
    aq = __syncthreads_or(aq);
    am = __syncthreads_or(am);
    if (threadIdx.x == 0) g_valid[b] = (aq && am) ? 1 : 0;
}

// ---------------- smem layout: 4-stage pipeline ----------------
#define KSZB (64 * 136 * 2)            // 17408 per stage, pitch 272B
#define VSZB (128 * 72 * 2)            // 18432 per stage, pitch 144B
#define KOFF 0
#define VOFF (4 * KSZB)                // 69632
#define MOFF (VOFF + 4 * VSZB)         // 143360
#define SMEM_TOTAL (MOFF + 4 * 256)    // 144384

// ---------------- Fused flash kernel: 2 chunks/iter, interleaved phases -------
__global__ void __launch_bounds__(256) flash_kernel(
    const float* __restrict__ qkey, const float* __restrict__ qval,
    const uint32_t* __restrict__ qmask, const uint32_t* __restrict__ mmask,
    float* __restrict__ out) {
    extern __shared__ char smem[];
    float* maskf = (float*)(smem + MOFF);
    const uint32_t smem_u32 = (uint32_t)__cvta_generic_to_shared(smem);

    const int tid = threadIdx.x;
    const int lane = tid & 31, warp = tid >> 5;
    const int g = lane >> 2, t = lane & 3;
    const int qw = warp * 16;
    const int b = blockIdx.z;
    const int qbase = blockIdx.x * 128;
    const int dvbase = blockIdx.y * 128;

    // B-operand ldmatrix lane offsets (16 rows, alternating +16B col)
    const int lrow = (lane >> 4) * 8 + (lane & 7);
    const int lcol = ((lane >> 3) & 1) * 16;
    const uint32_t koff_l = (uint32_t)(lrow * 272 + lcol);
    const uint32_t voff_l = (uint32_t)(lrow * 144 + lcol);

    // Per-warp persistent Q fragments (16 q rows x 128 d) from fp32 global.
    uint32_t aq[8][4];
    {
        const float* qkb = qkey + (size_t)b * DKDIM * NQ;
        const int q0g = qbase + qw + g;
#pragma unroll
        for (int ks = 0; ks < 8; ks++) {
            const int d0 = ks * 16 + 2 * t;
            const float* p0 = qkb + (size_t)d0 * NQ + q0g;
            const float* p8 = p0 + (size_t)8 * NQ;
            aq[ks][0] = bpack(p0[0], p0[NQ]);
            aq[ks][1] = bpack(p0[8], p0[NQ + 8]);
            aq[ks][2] = bpack(p8[0], p8[NQ]);
            aq[ks][3] = bpack(p8[8], p8[NQ + 8]);
        }
    }

    const __nv_bfloat16* ksrc_b = g_KT + (size_t)b * NM * DKDIM;
    const __nv_bfloat16* vsrc_b = g_VT + ((size_t)b * DVDIM + dvbase) * NM;
    const uint32_t* mmb = mmask + b * NM;

#define PREFETCH(ct)                                                           \
    do {                                                                       \
        const int bufi = (ct) & 3;                                             \
        const char* ksrc = (const char*)(ksrc_b + (size_t)(ct) * 64 * DKDIM);  \
        const uint32_t kdst = smem_u32 + KOFF + bufi * KSZB;                   \
        _Pragma("unroll") for (int k = 0; k < 4; k++) {                        \
            int idx = tid + k * 256;                                           \
            int m = idx >> 4, j = idx & 15;                                    \
            CPA16(kdst + m * 272 + j * 16, ksrc + m * 256 + j * 16);           \
        }                                                                      \
        const char* vsrc = (const char*)(vsrc_b + (size_t)(ct) * 64);          \
        const uint32_t vdst = smem_u32 + VOFF + bufi * VSZB;                   \
        _Pragma("unroll") for (int k = 0; k < 4; k++) {                        \
            int idx = tid + k * 256;                                           \
            int dv = idx >> 3, j = idx & 7;                                    \
            CPA16(vdst + dv * 144 + j * 16,                                    \
                  vsrc + (size_t)dv * (NM * 2) + j * 16);                      \
        }                                                                      \
        if (tid < 64)                                                          \
            maskf[bufi * 64 + tid] = (mmb[(ct) * 64 + tid] != 0) ? 1.f : 0.f;  \
    } while (0)

    // ---- QK for chunk ct into sc ----
#define QK_PHASE(ct, sc)                                                          \
    do {                                                                          \
        const uint32_t kfb = smem_u32 + KOFF + ((ct) & 3) * KSZB + koff_l;        \
        _Pragma("unroll") for (int j = 0; j < 8; j++)                             \
            _Pragma("unroll") for (int c = 0; c < 4; c++) (sc)[j][c] = 0.f;       \
        _Pragma("unroll") for (int ks = 0; ks < 8; ks++) {                        \
            _Pragma("unroll") for (int j = 0; j < 8; j += 2) {                    \
                uint32_t b0a, b1a, b0b, b1b;                                      \
                LDSM4(b0a, b1a, b0b, b1b, kfb + j * (8 * 272) + ks * 32);         \
                mma16816((sc)[j], aq[ks][0], aq[ks][1], aq[ks][2], aq[ks][3],     \
                         b0a, b1a);                                               \
                mma16816((sc)[j + 1], aq[ks][0], aq[ks][1], aq[ks][2],            \
                         aq[ks][3], b0b, b1b);                                    \
            }                                                                     \
        }                                                                         \
    } while (0)

    // ---- exp+mask+pack: sc -> pp[16], accumulate l ----
#define EXP_PHASE(ct, sc, pp)                                                     \
    do {                                                                          \
        const float* Mb = maskf + ((ct) & 3) * 64;                                \
        _Pragma("unroll") for (int j = 0; j < 8; j++) {                           \
            const float mf0 = Mb[j * 8 + 2 * t];                                  \
            const float mf1 = Mb[j * 8 + 2 * t + 1];                              \
            float p0 = ex2f((sc)[j][0] * KL2E) * mf0;                             \
            float p1 = ex2f((sc)[j][1] * KL2E) * mf1;                             \
            float p2 = ex2f((sc)[j][2] * KL2E) * mf0;                             \
            float p3 = ex2f((sc)[j][3] * KL2E) * mf1;                             \
            l0 += p0 + p1;                                                        \
            l1 += p2 + p3;                                                        \
            (pp)[(j >> 1) * 4 + (j & 1) * 2] = bpack(p0, p1);                     \
            (pp)[(j >> 1) * 4 + (j & 1) * 2 + 1] = bpack(p2, p3);                 \
        }                                                                         \
    } while (0)

    // ---- PV for chunk ct: O += P(pp) x V ----
#define PV_PHASE(ct, pp)                                                          \
    do {                                                                          \
        const uint32_t vfb = smem_u32 + VOFF + ((ct) & 3) * VSZB + voff_l;        \
        _Pragma("unroll") for (int jp = 0; jp < 4; jp++) {                        \
            _Pragma("unroll") for (int jv = 0; jv < 16; jv += 2) {                \
                uint32_t b0a, b1a, b0b, b1b;                                      \
                LDSM4(b0a, b1a, b0b, b1b, vfb + jv * (8 * 144) + jp * 32);        \
                mma16816(oacc[jv], (pp)[4 * jp], (pp)[4 * jp + 1],                \
                         (pp)[4 * jp + 2], (pp)[4 * jp + 3], b0a, b1a);           \
                mma16816(oacc[jv + 1], (pp)[4 * jp], (pp)[4 * jp + 1],            \
                         (pp)[4 * jp + 2], (pp)[4 * jp + 3], b0b, b1b);           \
            }                                                                     \
        }                                                                         \
    } while (0)

    float l0 = 0.f, l1 = 0.f;
    float oacc[16][4];
#pragma unroll
    for (int j = 0; j < 16; j++)
#pragma unroll
        for (int c = 0; c < 4; c++) oacc[j][c] = 0.f;

    PREFETCH(0);
    CPA_COMMIT();
    PREFETCH(1);
    CPA_COMMIT();

    for (int ct = 0; ct < NCHUNK; ct += 2) {
        CPA_WAIT0();        // chunks ct, ct+1 resident
        __syncthreads();    // prior reads of bufs (ct+2)&3,(ct+3)&3 complete
        if (ct + 2 < NCHUNK) {
            PREFETCH(ct + 2);
            CPA_COMMIT();
            PREFETCH(ct + 3);
            CPA_COMMIT();
        }

        float sc[8][4];
        uint32_t pp0[16], pp1[16];

        QK_PHASE(ct, sc);
        EXP_PHASE(ct, sc, pp0);       // MUFU; overlaps QK tail via scoreboard
        QK_PHASE(ct + 1, sc);         // independent of pp0 -> interleaves w/ exp
        PV_PHASE(ct, pp0);
        EXP_PHASE(ct + 1, sc, pp1);   // MUFU; overlaps PV(ct) MMAs
        PV_PHASE(ct + 1, pp1);
    }

    // ---- epilogue: reduce l across quad lanes, apply qmask, add qv ----
    l0 += __shfl_xor_sync(0xffffffffu, l0, 1);
    l0 += __shfl_xor_sync(0xffffffffu, l0, 2);
    l1 += __shfl_xor_sync(0xffffffffu, l1, 1);
    l1 += __shfl_xor_sync(0xffffffffu, l1, 2);

    const int q0 = qbase + qw + g;
    const int vb = g_valid[b];
    const float r0 = (vb != 0 && qmask[b * NQ + q0] != 0) ? 1.f / l0 : 0.f;
    const float r1 = (vb != 0 && qmask[b * NQ + q0 + 8] != 0) ? 1.f / l1 : 0.f;

    const float* qvb = qval + (size_t)b * DVDIM * NQ;
    float* ob = out + (size_t)b * DVDIM * NQ;
#pragma unroll
    for (int jv = 0; jv < 16; jv++) {
        const int dv0 = dvbase + jv * 8 + 2 * t;
        const size_t A = (size_t)dv0 * NQ + q0;
        ob[A] = qvb[A] + oacc[jv][0] * r0;
        ob[A + NQ] = qvb[A + NQ] + oacc[jv][1] * r0;
        ob[A + 8] = qvb[A + 8] + oacc[jv][2] * r1;
        ob[A + NQ + 8] = qvb[A + NQ + 8] + oacc[jv][3] * r1;
    }
}

extern "C" void kernel_launch(void* const* d_in, const int* in_sizes, int n_in,
                              void* d_out, int out_size) {
    const float* qkey = (const float*)d_in[0];
    const float* qval = (const float*)d_in[1];
    const uint32_t* qmask = (const uint32_t*)d_in[2];
    const float* mkey = (const float*)d_in[3];
    const float* mval = (const float*)d_in[4];
    const uint32_t* mmask = (const uint32_t*)d_in[5];
    float* out = (float*)d_out;

    static bool attr_set = false;
    if (!attr_set) {
        cudaFuncSetAttribute(flash_kernel,
                             cudaFuncAttributeMaxDynamicSharedMemorySize,
                             SMEM_TOTAL);
        attr_set = true;
    }

    convk_kernel<<<dim3(NM / 32, DKDIM / 32, BATCH), 256>>>(mkey);
    convv_kernel<<<(unsigned)((size_t)BATCH * DVDIM * NM / 4 / 256), 256>>>(mval);
    valid_kernel<<<BATCH, 256>>>(qmask, mmask);
    flash_kernel<<<dim3(NQ / 128, DVDIM / 128, BATCH), 256, SMEM_TOTAL>>>(
        qkey, qval, qmask, mmask, out);
}

// round 10
// speedup vs baseline: 1.5222x; 1.3881x over previous
#include <cuda_runtime.h>
#include <cuda_bf16.h>
#include <cstdint>

#define BATCH 4
#define DKDIM 128
#define DVDIM 512
#define NQ 4096
#define NM 8192
#define NCHUNK (NM / 64)
#define KL2E (0.08838834764831843f * 1.4426950408889634f)

// Pre-converted bf16 operands (device globals, allocation-guard-safe)
__device__ __nv_bfloat16 g_KT[(size_t)BATCH * NM * DKDIM];   // [b][m][d]
__device__ __nv_bfloat16 g_VT[(size_t)BATCH * DVDIM * NM];   // [b][dv][m]
__device__ int g_valid[BATCH];

static __device__ __forceinline__ void mma16816(float c[4], uint32_t a0, uint32_t a1,
                                                uint32_t a2, uint32_t a3,
                                                uint32_t b0, uint32_t b1) {
    asm volatile(
        "mma.sync.aligned.m16n8k16.row.col.f32.bf16.bf16.f32 "
        "{%0,%1,%2,%3}, {%4,%5,%6,%7}, {%8,%9}, {%0,%1,%2,%3};\n"
        : "+f"(c[0]), "+f"(c[1]), "+f"(c[2]), "+f"(c[3])
        : "r"(a0), "r"(a1), "r"(a2), "r"(a3), "r"(b0), "r"(b1));
}

#define LDSM4(r0, r1, r2, r3, addr)                                          \
    asm volatile(                                                            \
        "ldmatrix.sync.aligned.m8n8.x4.shared.b16 {%0,%1,%2,%3}, [%4];"      \
        : "=r"(r0), "=r"(r1), "=r"(r2), "=r"(r3) : "r"(addr))

static __device__ __forceinline__ float ex2f(float x) {
    float y;
    asm("ex2.approx.ftz.f32 %0, %1;" : "=f"(y) : "f"(x));
    return y;
}

static __device__ __forceinline__ uint32_t bpack(float lo, float hi) {
    __nv_bfloat162 h = __floats2bfloat162_rn(lo, hi);
    return *reinterpret_cast<uint32_t*>(&h);
}

#define CPA16(dst, src) \
    asm volatile("cp.async.ca.shared.global [%0], [%1], 16;\n" :: "r"(dst), "l"(src))
#define CPA_COMMIT() asm volatile("cp.async.commit_group;\n")
#define CPA_WAIT1() asm volatile("cp.async.wait_group 1;\n")

// ---------------- K0a: transpose+convert mkey -> g_KT[b][m][d] ----------------
__global__ void __launch_bounds__(256) convk_kernel(const float* __restrict__ mk) {
    __shared__ float tile[32][33];
    const int b = blockIdx.z;
    const int m0 = blockIdx.x * 32, d0 = blockIdx.y * 32;
    const int tx = threadIdx.x & 31, ty = threadIdx.x >> 5;
    const float* src = mk + ((size_t)b * DKDIM + d0) * NM + m0;
#pragma unroll
    for (int i = ty; i < 32; i += 8) tile[i][tx] = src[(size_t)i * NM + tx];
    __syncthreads();
    __nv_bfloat16* dst = g_KT + ((size_t)b * NM + m0) * DKDIM + d0;
#pragma unroll
    for (int i = ty; i < 32; i += 8)
        dst[(size_t)i * DKDIM + tx] = __float2bfloat16(tile[tx][i]);
}

// ---------------- K0b: convert mval -> g_VT (same layout) ----------------
__global__ void __launch_bounds__(256) convv_kernel(const float* __restrict__ mv) {
    const size_t i = ((size_t)blockIdx.x * 256 + threadIdx.x) * 4;
    float4 v = *(const float4*)&mv[i];
    uint2 pk = make_uint2(bpack(v.x, v.y), bpack(v.z, v.w));
    *(uint2*)&g_VT[i] = pk;
}

// ---------------- K0c: per-batch validity flags ----------------
__global__ void valid_kernel(const uint32_t* __restrict__ qm,
                             const uint32_t* __restrict__ mm) {
    int b = blockIdx.x;
    int aq = 0, am = 0;
    for (int i = threadIdx.x; i < NQ; i += blockDim.x) aq |= (qm[b * NQ + i] != 0);
    for (int i = threadIdx.x; i < NM; i += blockDim.x) am |= (mm[b * NM + i] != 0);
    aq = __syncthreads_or(aq);
    am = __syncthreads_or(am);
    if (threadIdx.x == 0) g_valid[b] = (aq && am) ? 1 : 0;
}

// ---------------- smem layout: 3-stage pipeline, dv-slice 256 ----------------
#define KSZB (64 * 136 * 2)            // 17408 per stage, pitch 272B
#define VSZB (256 * 72 * 2)            // 36864 per stage, pitch 144B
#define KOFF 0
#define VOFF (3 * KSZB)                // 52224
#define MOFF (VOFF + 3 * VSZB)         // 162816
#define SMEM_TOTAL (MOFF + 3 * 256)    // 163584

// ---------------- Fused flash kernel: dv-slice 256 ----------------
__global__ void __launch_bounds__(256) flash_kernel(
    const float* __restrict__ qkey, const float* __restrict__ qval,
    const uint32_t* __restrict__ qmask, const uint32_t* __restrict__ mmask,
    float* __restrict__ out) {
    extern __shared__ char smem[];
    float* maskf = (float*)(smem + MOFF);
    const uint32_t smem_u32 = (uint32_t)__cvta_generic_to_shared(smem);

    const int tid = threadIdx.x;
    const int lane = tid & 31, warp = tid >> 5;
    const int g = lane >> 2, t = lane & 3;
    const int qw = warp * 16;
    const int b = blockIdx.z;
    const int qbase = blockIdx.x * 128;
    const int dvbase = blockIdx.y * 256;

    // B-operand ldmatrix lane offsets (16 rows, alternating +16B col)
    const int lrow = (lane >> 4) * 8 + (lane & 7);
    const int lcol = ((lane >> 3) & 1) * 16;
    const uint32_t koff_l = (uint32_t)(lrow * 272 + lcol);
    const uint32_t voff_l = (uint32_t)(lrow * 144 + lcol);

    // Per-warp persistent Q fragments (16 q rows x 128 d) from fp32 global.
    uint32_t aq[8][4];
    {
        const float* qkb = qkey + (size_t)b * DKDIM * NQ;
        const int q0g = qbase + qw + g;
#pragma unroll
        for (int ks = 0; ks < 8; ks++) {
            const int d0 = ks * 16 + 2 * t;
            const float* p0 = qkb + (size_t)d0 * NQ + q0g;
            const float* p8 = p0 + (size_t)8 * NQ;
            aq[ks][0] = bpack(p0[0], p0[NQ]);
            aq[ks][1] = bpack(p0[8], p0[NQ + 8]);
            aq[ks][2] = bpack(p8[0], p8[NQ]);
            aq[ks][3] = bpack(p8[8], p8[NQ + 8]);
        }
    }

    const __nv_bfloat16* ksrc_b = g_KT + (size_t)b * NM * DKDIM;
    const __nv_bfloat16* vsrc_b = g_VT + ((size_t)b * DVDIM + dvbase) * NM;
    const uint32_t* mmb = mmask + b * NM;

#define PREFETCH(ct)                                                           \
    do {                                                                       \
        const int bufi = (ct) % 3;                                             \
        const char* ksrc = (const char*)(ksrc_b + (size_t)(ct) * 64 * DKDIM);  \
        const uint32_t kdst = smem_u32 + KOFF + bufi * KSZB;                   \
        _Pragma("unroll") for (int k = 0; k < 4; k++) {                        \
            int idx = tid + k * 256;                                           \
            int m = idx >> 4, j = idx & 15;                                    \
            CPA16(kdst + m * 272 + j * 16, ksrc + m * 256 + j * 16);           \
        }                                                                      \
        const char* vsrc = (const char*)(vsrc_b + (size_t)(ct) * 64);          \
        const uint32_t vdst = smem_u32 + VOFF + bufi * VSZB;                   \
        _Pragma("unroll") for (int k = 0; k < 8; k++) {                        \
            int idx = tid + k * 256;                                           \
            int dv = idx >> 3, j = idx & 7;                                    \
            CPA16(vdst + dv * 144 + j * 16,                                    \
                  vsrc + (size_t)dv * (NM * 2) + j * 16);                      \
        }                                                                      \
        if (tid < 64)                                                          \
            maskf[bufi * 64 + tid] = (mmb[(ct) * 64 + tid] != 0) ? 1.f : 0.f;  \
    } while (0)

    float l0 = 0.f, l1 = 0.f;
    float oacc[32][4];
#pragma unroll
    for (int j = 0; j < 32; j++)
#pragma unroll
        for (int c = 0; c < 4; c++) oacc[j][c] = 0.f;

    PREFETCH(0);
    CPA_COMMIT();
    __syncthreads();  // maskf[0] (plain store) visible before first compute
    PREFETCH(1);
    CPA_COMMIT();

    for (int ct = 0; ct < NCHUNK; ct++) {
        CPA_WAIT1();
        __syncthreads();
        if (ct + 2 < NCHUNK) PREFETCH(ct + 2);
        CPA_COMMIT();  // unconditional: uniform group accounting

        const int bufi = ct % 3;
        const uint32_t kfb = smem_u32 + KOFF + bufi * KSZB + koff_l;
        const uint32_t vfb = smem_u32 + VOFF + bufi * VSZB + voff_l;
        const float* Mb = maskf + bufi * 64;

        // ---- QK: S[16q x 64m], K fragments via ldmatrix.x4 ----
        float sc[8][4];
#pragma unroll
        for (int j = 0; j < 8; j++)
#pragma unroll
            for (int c = 0; c < 4; c++) sc[j][c] = 0.f;
#pragma unroll
        for (int ks = 0; ks < 8; ks++) {
#pragma unroll
            for (int j = 0; j < 8; j += 2) {
                uint32_t b0a, b1a, b0b, b1b;
                LDSM4(b0a, b1a, b0b, b1b, kfb + j * (8 * 272) + ks * 32);
                mma16816(sc[j], aq[ks][0], aq[ks][1], aq[ks][2], aq[ks][3], b0a, b1a);
                mma16816(sc[j + 1], aq[ks][0], aq[ks][1], aq[ks][2], aq[ks][3], b0b, b1b);
            }
        }

        // ---- softmax numerator: p = exp2(s*KL2E) * mask ----
#pragma unroll
        for (int j = 0; j < 8; j++) {
            const float mf0 = Mb[j * 8 + 2 * t];
            const float mf1 = Mb[j * 8 + 2 * t + 1];
            sc[j][0] = ex2f(sc[j][0] * KL2E) * mf0;
            sc[j][1] = ex2f(sc[j][1] * KL2E) * mf1;
            sc[j][2] = ex2f(sc[j][2] * KL2E) * mf0;
            sc[j][3] = ex2f(sc[j][3] * KL2E) * mf1;
            l0 += sc[j][0] + sc[j][1];
            l1 += sc[j][2] + sc[j][3];
        }

        // ---- PV: O[16q x 256dv] += P * V, V fragments via ldmatrix.x4 ----
#pragma unroll
        for (int jp = 0; jp < 4; jp++) {
            uint32_t a0 = bpack(sc[2 * jp][0], sc[2 * jp][1]);
            uint32_t a1 = bpack(sc[2 * jp][2], sc[2 * jp][3]);
            uint32_t a2 = bpack(sc[2 * jp + 1][0], sc[2 * jp + 1][1]);
            uint32_t a3 = bpack(sc[2 * jp + 1][2], sc[2 * jp + 1][3]);
#pragma unroll
            for (int jv = 0; jv < 32; jv += 2) {
                uint32_t b0a, b1a, b0b, b1b;
                LDSM4(b0a, b1a, b0b, b1b, vfb + jv * (8 * 144) + jp * 32);
                mma16816(oacc[jv], a0, a1, a2, a3, b0a, b1a);
                mma16816(oacc[jv + 1], a0, a1, a2, a3, b0b, b1b);
            }
        }
    }

    // ---- epilogue: reduce l across quad lanes, apply qmask, add qv ----
    l0 += __shfl_xor_sync(0xffffffffu, l0, 1);
    l0 += __shfl_xor_sync(0xffffffffu, l0, 2);
    l1 += __shfl_xor_sync(0xffffffffu, l1, 1);
    l1 += __shfl_xor_sync(0xffffffffu, l1, 2);

    const int q0 = qbase + qw + g;
    const int vb = g_valid[b];
    const float r0 = (vb != 0 && qmask[b * NQ + q0] != 0) ? 1.f / l0 : 0.f;
    const float r1 = (vb != 0 && qmask[b * NQ + q0 + 8] != 0) ? 1.f / l1 : 0.f;

    const float* qvb = qval + (size_t)b * DVDIM * NQ;
    float* ob = out + (size_t)b * DVDIM * NQ;
#pragma unroll
    for (int jv = 0; jv < 32; jv++) {
        const int dv0 = dvbase + jv * 8 + 2 * t;
        const size_t A = (size_t)dv0 * NQ + q0;
        ob[A] = qvb[A] + oacc[jv][0] * r0;
        ob[A + NQ] = qvb[A + NQ] + oacc[jv][1] * r0;
        ob[A + 8] = qvb[A + 8] + oacc[jv][2] * r1;
        ob[A + NQ + 8] = qvb[A + NQ + 8] + oacc[jv][3] * r1;
    }
}

extern "C" void kernel_launch(void* const* d_in, const int* in_sizes, int n_in,
                              void* d_out, int out_size) {
    const float* qkey = (const float*)d_in[0];
    const float* qval = (const float*)d_in[1];
    const uint32_t* qmask = (const uint32_t*)d_in[2];
    const float* mkey = (const float*)d_in[3];
    const float* mval = (const float*)d_in[4];
    const uint32_t* mmask = (const uint32_t*)d_in[5];
    float* out = (float*)d_out;

    static bool attr_set = false;
    if (!attr_set) {
        cudaFuncSetAttribute(flash_kernel,
                             cudaFuncAttributeMaxDynamicSharedMemorySize,
                             SMEM_TOTAL);
        attr_set = true;
    }

    convk_kernel<<<dim3(NM / 32, DKDIM / 32, BATCH), 256>>>(mkey);
    convv_kernel<<<(unsigned)((size_t)BATCH * DVDIM * NM / 4 / 256), 256>>>(mval);
    valid_kernel<<<BATCH, 256>>>(qmask, mmask);
    flash_kernel<<<dim3(NQ / 128, DVDIM / 256, BATCH), 256, SMEM_TOTAL>>>(
        qkey, qval, qmask, mmask, out);
}